// round 15
// baseline (speedup 1.0000x reference)
#include <cuda_runtime.h>
#include <cuda_fp16.h>
#include <cstdint>

#define ND 128
#define NA 512
#define NB 512
#define K1 256

// ---- smem layout (bytes) ----
#define OFF_E16 0          // two E fp16 buffers, 128x40 halves each
#define E16SZ   10240
#define ESTRIDE 40
#define OFF_W   20480      // GEMM1: 4-slot ring of 8704B; GEMM2: contiguous 128x136h W2
#define W1SLOT  8704       // 32 rows x 136 halves x 2B
#define WSTRIDE 136
#define OFF_SB  55296      // sum_b staging 8x128 f32
#define SMEM_BYTES 59392

// device scratch (no allocation allowed)
__device__ float g_preA[NA * ND];
__device__ float g_preB[NB * ND];
__device__ float g_sumA[NA * ND];
__device__ float g_sumB[NB * ND];
__device__ __align__(16) __half g_W1h[K1 * ND];  // [k][n] = half(We1[256+k][n])
__device__ __align__(16) __half g_W2h[ND * ND];  // [k][n] = half(We2[k][n])

// ---------------------------------------------------------------------------
__device__ __forceinline__ void cp_async16(uint32_t saddr, const void* gptr) {
    asm volatile("cp.async.cg.shared.global [%0], [%1], 16;\n" :: "r"(saddr), "l"(gptr));
}
__device__ __forceinline__ void cp_commit() { asm volatile("cp.async.commit_group;\n"); }
template <int N> __device__ __forceinline__ void cp_wait() {
    asm volatile("cp.async.wait_group %0;\n" :: "n"(N));
}

__device__ __forceinline__ uint32_t h2_bits(__half2 h) {
    return *reinterpret_cast<uint32_t*>(&h);
}

#define LDSM_X4(r, addr) \
    asm volatile("ldmatrix.sync.aligned.m8n8.x4.shared.b16 {%0,%1,%2,%3}, [%4];" \
        : "=r"((r)[0]), "=r"((r)[1]), "=r"((r)[2]), "=r"((r)[3]) : "r"(addr))

#define LDSM_X4T(r, addr) \
    asm volatile("ldmatrix.sync.aligned.m8n8.x4.trans.shared.b16 {%0,%1,%2,%3}, [%4];" \
        : "=r"((r)[0]), "=r"((r)[1]), "=r"((r)[2]), "=r"((r)[3]) : "r"(addr))

#define MMA16816(d, a, b) \
    asm volatile("mma.sync.aligned.m16n8k16.row.col.f32.f16.f16.f32 " \
        "{%0,%1,%2,%3}, {%4,%5,%6,%7}, {%8,%9}, {%0,%1,%2,%3};" \
        : "+f"((d)[0]), "+f"((d)[1]), "+f"((d)[2]), "+f"((d)[3]) \
        : "r"((a)[0]), "r"((a)[1]), "r"((a)[2]), "r"((a)[3]), "r"((b)[0]), "r"((b)[1]))

// ---------------------------------------------------------------------------
// pre-kernels (split 3 ways so edge_kernel sits at launch index 3 for ncu)
// ---------------------------------------------------------------------------
__global__ void wconv_kernel(const float* __restrict__ We1,
                             const float* __restrict__ We2) {
    const int i = blockIdx.x;     // 0..255
    const int n = threadIdx.x;
    g_W1h[i * ND + n] = __float2half(We1[(size_t)(2 * ND + i) * ND + n]);
    if (i < 128) g_W2h[i * ND + n] = __float2half(We2[(size_t)i * ND + n]);
}

__global__ void pre_kernel(const float* __restrict__ na,
                           const float* __restrict__ nb,
                           const float* __restrict__ We1,
                           const float* __restrict__ be1) {
    __shared__ float sa[ND];
    __shared__ float sb[ND];
    const int i = blockIdx.x;
    const int n = threadIdx.x;
    sa[n] = na[i * ND + n];
    sb[n] = nb[i * ND + n];
    __syncthreads();
    float accA = be1[n];
    float accB = 0.f;
#pragma unroll 8
    for (int k = 0; k < ND; k++) {
        accA += sa[k] * We1[k * ND + n];
        accB += sb[k] * We1[(ND + k) * ND + n];
    }
    g_preA[i * ND + n] = accA;
    g_preB[i * ND + n] = accB;
}

__global__ void zsum_kernel() {
    const int i = blockIdx.x * 128 + threadIdx.x;
    g_sumA[i] = 0.f;
    g_sumB[i] = 0.f;
}

// ---------------------------------------------------------------------------
// edge kernel: tile 16a x 8b (= 128 rows) x N128, fp16 mma.m16n8k16.
// warp wm = warp (0..7) owns rows [wm*16, wm*16+16) x ALL 128 cols.
// C-fragments of GEMM1 double as A-fragments of GEMM2 (no h smem round-trip).
// ---------------------------------------------------------------------------
extern __shared__ __align__(16) char smem[];

__global__ __launch_bounds__(256, 2)
void edge_kernel(const float* __restrict__ E,
                 const float* __restrict__ be2,
                 float* __restrict__ out) {
    const int tid  = threadIdx.x;
    const int lane = tid & 31;
    const int wm   = tid >> 5;          // warp = row block of 16
    const int a0   = blockIdx.y * 16;
    const int b0   = blockIdx.x * 8;

    const uint32_t su = (uint32_t)__cvta_generic_to_shared(smem);
    const int lr  = lane & 15;
    const int lk8 = (lane >> 4) * 8;
    const int g   = lane >> 2;          // 0..7  (b within tile / row-in-group)
    const int t   = lane & 3;

    float acc[16][4];
#pragma unroll
    for (int nf = 0; nf < 16; nf++)
#pragma unroll
        for (int c = 0; c < 4; c++) acc[nf][c] = 0.f;

    // E LDG prefetch registers: one k32 chunk = 4 float4 per thread
    const int erow = tid >> 3;
    const int eq   = tid & 7;
    float4 rg[4];

#define LDG_E_CHUNK(kc) do { \
    _Pragma("unroll") \
    for (int u = 0; u < 4; u++) { \
        const int r = erow + 32 * u; \
        rg[u] = *reinterpret_cast<const float4*>( \
            E + ((size_t)(a0 + (r >> 3)) * 512 + (b0 + (r & 7))) * K1 + (kc) + eq * 4); \
    } } while (0)

#define STS_E_CHUNK(buf) do { \
    char* eb = smem + OFF_E16 + (buf) * E16SZ; \
    _Pragma("unroll") \
    for (int u = 0; u < 4; u++) { \
        const int r = erow + 32 * u; \
        half2* p = reinterpret_cast<half2*>(eb + ((size_t)r * ESTRIDE + eq * 4) * 2); \
        p[0] = __floats2half2_rn(rg[u].x, rg[u].y); \
        p[1] = __floats2half2_rn(rg[u].z, rg[u].w); \
    } } while (0)

// 4-slot W1 ring: stage chunk ci2 into slot ci2&3 (distance 2 from live slot)
#define STAGE_W1(ci2) do { \
    const uint32_t sbase = su + OFF_W + ((ci2) & 3) * W1SLOT; \
    _Pragma("unroll") \
    for (int u = 0; u < 2; u++) { \
        const int ii = tid + u * 256; \
        const int rw = ii >> 4, sg = ii & 15; \
        cp_async16(sbase + rw * (WSTRIDE * 2) + sg * 16, \
                   reinterpret_cast<const char*>(g_W1h) + ((ci2) * 32 + rw) * 256 + sg * 16); \
    } cp_commit(); } while (0)

    // prologue
    LDG_E_CHUNK(0);
    STS_E_CHUNK(0);
    STAGE_W1(0);
    LDG_E_CHUNK(32);
    STAGE_W1(1);

    // ---------------- GEMM1: 8 chunks of k=32 ----------------
#pragma unroll 1
    for (int ci = 0; ci < 8; ci++) {
        if (ci < 7) cp_wait<1>(); else cp_wait<0>();
        __syncthreads();

        if (ci < 7) STS_E_CHUNK((ci + 1) & 1);
        if (ci + 2 < 8) {
            LDG_E_CHUNK((ci + 2) * 32);
            STAGE_W1(ci + 2);
        }

        const uint32_t ea = su + OFF_E16 + (ci & 1) * E16SZ;
        const uint32_t wb = su + OFF_W + (ci & 3) * W1SLOT;
#pragma unroll
        for (int s = 0; s < 2; s++) {
            uint32_t af[4];
            LDSM_X4(af, ea + ((wm * 16 + lr) * ESTRIDE + s * 16 + lk8) * 2);
#pragma unroll
            for (int q = 0; q < 8; q++) {
                uint32_t bf[4];
                LDSM_X4T(bf, wb + ((s * 16 + lr) * WSTRIDE + q * 16 + lk8) * 2);
                MMA16816(acc[2 * q + 0], af, bf + 0);
                MMA16816(acc[2 * q + 1], af, bf + 2);
            }
        }
    }
    __syncthreads();   // all ldsm of E16 / W1 ring done everywhere

    // stage ALL of W2 into the (now dead) W region: contiguous rows, stride 136h
#pragma unroll
    for (int u = 0; u < 8; u++) {
        const int ii = tid + u * 256;          // 0..2047
        const int rw = ii >> 4, sg = ii & 15;  // rw 0..127
        cp_async16(su + OFF_W + rw * (WSTRIDE * 2) + sg * 16,
                   reinterpret_cast<const char*>(g_W2h) + rw * 256 + sg * 16);
    }
    cp_commit();

    // zero sum_b staging
    {
        float* sbp = reinterpret_cast<float*>(smem + OFF_SB);
        for (int i = tid; i < 8 * ND; i += 256) sbp[i] = 0.f;
    }

    // -------- epilogue 1: h = fp16(relu(acc + preA + preB)) kept in registers --
    // thread owns rows r1 = wm*16+g (a = a0+2wm, b = b0+g) and r2 = r1+8 (a+1, same b)
    uint32_t ah[32];
    {
        const int a1 = a0 + 2 * wm;
        const float* pA1 = g_preA + (size_t)a1 * ND;
        const float* pA2 = g_preA + (size_t)(a1 + 1) * ND;
        const float* pB  = g_preB + (size_t)(b0 + g) * ND;
#pragma unroll
        for (int nf = 0; nf < 16; nf++) {
            const int col = nf * 8 + 2 * t;
            float2 qa1 = *reinterpret_cast<const float2*>(pA1 + col);
            float2 qa2 = *reinterpret_cast<const float2*>(pA2 + col);
            float2 qb  = *reinterpret_cast<const float2*>(pB + col);
            float v0 = fmaxf(acc[nf][0] + qa1.x + qb.x, 0.f);
            float v1 = fmaxf(acc[nf][1] + qa1.y + qb.y, 0.f);
            float v2 = fmaxf(acc[nf][2] + qa2.x + qb.x, 0.f);
            float v3 = fmaxf(acc[nf][3] + qa2.y + qb.y, 0.f);
            ah[2 * nf + 0] = h2_bits(__floats2half2_rn(v0, v1));
            ah[2 * nf + 1] = h2_bits(__floats2half2_rn(v2, v3));
        }
    }
    // reset accumulators for GEMM2
#pragma unroll
    for (int nf = 0; nf < 16; nf++)
#pragma unroll
        for (int c = 0; c < 4; c++) acc[nf][c] = 0.f;

    cp_wait<0>();
    __syncthreads();   // W2 staged + sbp zeroed

    // ---------------- GEMM2: h(16x128 regs) @ W2(128x128), no barriers -------
#pragma unroll
    for (int ks = 0; ks < 8; ks++) {
#pragma unroll
        for (int q = 0; q < 8; q++) {
            uint32_t bf[4];
            LDSM_X4T(bf, su + OFF_W + ((ks * 16 + lr) * WSTRIDE + q * 16 + lk8) * 2);
            MMA16816(acc[2 * q + 0], &ah[4 * ks], bf + 0);
            MMA16816(acc[2 * q + 1], &ah[4 * ks], bf + 2);
        }
    }

    // -------- epilogue 2: out = relu(acc + be2); sums --------
    {
        const int a1 = a0 + 2 * wm;
        const int bI = b0 + g;
        float* orow1 = out + ((size_t)a1 * 512 + bI) * ND;
        float* orow2 = out + ((size_t)(a1 + 1) * 512 + bI) * ND;
        float* sbp = reinterpret_cast<float*>(smem + OFF_SB);
#pragma unroll
        for (int nf = 0; nf < 16; nf++) {
            const int col = nf * 8 + 2 * t;
            float2 be = *reinterpret_cast<const float2*>(be2 + col);
            float w0 = fmaxf(acc[nf][0] + be.x, 0.f);
            float w1 = fmaxf(acc[nf][1] + be.y, 0.f);
            float w2 = fmaxf(acc[nf][2] + be.x, 0.f);
            float w3 = fmaxf(acc[nf][3] + be.y, 0.f);
            *reinterpret_cast<float2*>(orow1 + col) = make_float2(w0, w1);
            *reinterpret_cast<float2*>(orow2 + col) = make_float2(w2, w3);
            // sum over b (reduce across lane groups g): rows a1 and a1+1
            float s0 = w0, s1 = w1, s2 = w2, s3 = w3;
#pragma unroll
            for (int m = 4; m <= 16; m <<= 1) {
                s0 += __shfl_xor_sync(0xffffffffu, s0, m);
                s1 += __shfl_xor_sync(0xffffffffu, s1, m);
                s2 += __shfl_xor_sync(0xffffffffu, s2, m);
                s3 += __shfl_xor_sync(0xffffffffu, s3, m);
            }
            if (lane < 4) {
                atomicAdd(&g_sumA[(size_t)a1 * ND + col], s0);
                atomicAdd(&g_sumA[(size_t)a1 * ND + col + 1], s1);
                atomicAdd(&g_sumA[(size_t)(a1 + 1) * ND + col], s2);
                atomicAdd(&g_sumA[(size_t)(a1 + 1) * ND + col + 1], s3);
            }
            // sum over a within thread (rows share b) -> smem partial per (b, col)
            atomicAdd(&sbp[g * ND + col], w0 + w2);
            atomicAdd(&sbp[g * ND + col + 1], w1 + w3);
        }
    }
    __syncthreads();
    {
        const float* sbp = reinterpret_cast<const float*>(smem + OFF_SB);
        for (int i = tid; i < 8 * ND; i += 256)
            atomicAdd(&g_sumB[(size_t)(b0 + (i >> 7)) * ND + (i & 127)], sbp[i]);
    }
}

// ---------------------------------------------------------------------------
// Final node MLP: rows 0..511 = nodes_a, 512..1023 = nodes_b
// ---------------------------------------------------------------------------
__global__ void nodes_kernel(const float* __restrict__ na,
                             const float* __restrict__ nb,
                             const float* __restrict__ Wn1,
                             const float* __restrict__ bn1,
                             const float* __restrict__ Wn2,
                             const float* __restrict__ bn2,
                             float* __restrict__ out) {
    __shared__ float x[2 * ND];
    __shared__ float h[ND];
    const int row = blockIdx.x;
    const int n   = threadIdx.x;
    const int idx = row & 511;
    const float* emb  = (row < 512) ? na : nb;
    const float* sums = (row < 512) ? g_sumA : g_sumB;
    x[n]      = emb[idx * ND + n];
    x[ND + n] = sums[idx * ND + n];
    __syncthreads();
    float v = bn1[n];
#pragma unroll 8
    for (int k = 0; k < 2 * ND; k++) v += x[k] * Wn1[k * ND + n];
    h[n] = fmaxf(v, 0.f);
    __syncthreads();
    float v2 = bn2[n];
#pragma unroll 8
    for (int k = 0; k < ND; k++) v2 += h[k] * Wn2[k * ND + n];
    out[(size_t)NA * NB * ND + (size_t)row * ND + n] = fmaxf(v2, 0.f);
}

// ---------------------------------------------------------------------------
extern "C" void kernel_launch(void* const* d_in, const int* in_sizes, int n_in,
                              void* d_out, int out_size) {
    const float* E   = (const float*)d_in[0];
    const float* na  = (const float*)d_in[1];
    const float* nb  = (const float*)d_in[2];
    const float* We1 = (const float*)d_in[3];
    const float* be1 = (const float*)d_in[4];
    const float* We2 = (const float*)d_in[5];
    const float* be2 = (const float*)d_in[6];
    const float* Wn1 = (const float*)d_in[7];
    const float* bn1 = (const float*)d_in[8];
    const float* Wn2 = (const float*)d_in[9];
    const float* bn2 = (const float*)d_in[10];
    float* out = (float*)d_out;

    cudaFuncSetAttribute(edge_kernel, cudaFuncAttributeMaxDynamicSharedMemorySize, SMEM_BYTES);

    // edge_kernel at launch index 3 -> profiled by ncu (-s 5 -c 1 lands on index 3)
    wconv_kernel<<<256, 128>>>(We1, We2);
    pre_kernel<<<512, 128>>>(na, nb, We1, be1);
    zsum_kernel<<<512, 128>>>();
    edge_kernel<<<dim3(64, 32), 256, SMEM_BYTES>>>(E, be2, out);
    nodes_kernel<<<1024, 128>>>(na, nb, Wn1, bn1, Wn2, bn2, out);
}

// round 17
// speedup vs baseline: 1.2343x; 1.2343x over previous
#include <cuda_runtime.h>
#include <cuda_fp16.h>
#include <cstdint>

#define ND 128
#define NA 512
#define NB 512
#define K1 256

// ---- smem layout (bytes) ----
#define OFF_E16 0          // two E fp16 buffers, 128x40 halves each
#define E16SZ   10240
#define ESTRIDE 40
#define OFF_W   20480      // GEMM1: 4-slot ring of 8704B; GEMM2: contiguous 128x136h W2
#define W1SLOT  8704       // 32 rows x 136 halves x 2B
#define WSTRIDE 136
#define OFF_H   0          // h fp16 tile 128x136h aliases E region? NO -- h needs own region
// NOTE: h tile 128x136 halves = 34816B. E region is only 20480B, so h gets its own
// region after SBW to avoid aliasing W2 (which GEMM2 needs live).
#define OFF_SBW 55296      // per-wm sum_b slices: 4 x 8 x 128 f32 = 16KB
#define OFF_HT  71680      // h fp16 tile 128x136h = 34816B
#define HSTRIDE 136
#define SMEM_BYTES 106496  // 71680 + 34816 -> 2 CTAs/SM (213KB < 228KB)

// device scratch (no allocation allowed)
__device__ float g_preA[NA * ND];
__device__ float g_preB[NB * ND];
__device__ float g_sumA[NA * ND];
__device__ float g_sumB[NB * ND];
__device__ __align__(16) __half g_W1h[K1 * ND];  // [k][n] = half(We1[256+k][n])
__device__ __align__(16) __half g_W2h[ND * ND];  // [k][n] = half(We2[k][n])

// ---------------------------------------------------------------------------
__device__ __forceinline__ void cp_async16(uint32_t saddr, const void* gptr) {
    asm volatile("cp.async.cg.shared.global [%0], [%1], 16;\n" :: "r"(saddr), "l"(gptr));
}
__device__ __forceinline__ void cp_commit() { asm volatile("cp.async.commit_group;\n"); }
template <int N> __device__ __forceinline__ void cp_wait() {
    asm volatile("cp.async.wait_group %0;\n" :: "n"(N));
}

__device__ __forceinline__ uint32_t h2_bits(__half2 h) {
    return *reinterpret_cast<uint32_t*>(&h);
}

#define LDSM_X4(r, addr) \
    asm volatile("ldmatrix.sync.aligned.m8n8.x4.shared.b16 {%0,%1,%2,%3}, [%4];" \
        : "=r"((r)[0]), "=r"((r)[1]), "=r"((r)[2]), "=r"((r)[3]) : "r"(addr))

#define LDSM_X4T(r, addr) \
    asm volatile("ldmatrix.sync.aligned.m8n8.x4.trans.shared.b16 {%0,%1,%2,%3}, [%4];" \
        : "=r"((r)[0]), "=r"((r)[1]), "=r"((r)[2]), "=r"((r)[3]) : "r"(addr))

#define MMA16816(d, a, b) \
    asm volatile("mma.sync.aligned.m16n8k16.row.col.f32.f16.f16.f32 " \
        "{%0,%1,%2,%3}, {%4,%5,%6,%7}, {%8,%9}, {%0,%1,%2,%3};" \
        : "+f"((d)[0]), "+f"((d)[1]), "+f"((d)[2]), "+f"((d)[3]) \
        : "r"((a)[0]), "r"((a)[1]), "r"((a)[2]), "r"((a)[3]), "r"((b)[0]), "r"((b)[1]))

// ---------------------------------------------------------------------------
// pre-kernels (split so edge_kernel sits at launch index 3 for ncu -s 5)
// ---------------------------------------------------------------------------
__global__ void wconv_kernel(const float* __restrict__ We1,
                             const float* __restrict__ We2) {
    const int i = blockIdx.x;     // 0..255
    const int n = threadIdx.x;
    g_W1h[i * ND + n] = __float2half(We1[(size_t)(2 * ND + i) * ND + n]);
    if (i < 128) g_W2h[i * ND + n] = __float2half(We2[(size_t)i * ND + n]);
}

__global__ void pre_kernel(const float* __restrict__ na,
                           const float* __restrict__ nb,
                           const float* __restrict__ We1,
                           const float* __restrict__ be1) {
    __shared__ float sa[ND];
    __shared__ float sb[ND];
    const int i = blockIdx.x;
    const int n = threadIdx.x;
    sa[n] = na[i * ND + n];
    sb[n] = nb[i * ND + n];
    __syncthreads();
    float accA = be1[n];
    float accB = 0.f;
#pragma unroll 8
    for (int k = 0; k < ND; k++) {
        accA += sa[k] * We1[k * ND + n];
        accB += sb[k] * We1[(ND + k) * ND + n];
    }
    g_preA[i * ND + n] = accA;
    g_preB[i * ND + n] = accB;
}

__global__ void zsum_kernel() {
    const int i = blockIdx.x * 128 + threadIdx.x;
    g_sumA[i] = 0.f;
    g_sumB[i] = 0.f;
}

// ---------------------------------------------------------------------------
// edge kernel: tile 16a x 8b (= 128 rows) x N128, fp16 mma.m16n8k16.
// warps: wm = warp>>1 (row block of 32), wn = warp&1 (col block of 64).
// (R9 layout: ldsm-optimal 6 ldsm per warp-k16.)
// ---------------------------------------------------------------------------
extern __shared__ __align__(16) char smem[];

__global__ __launch_bounds__(256, 2)
void edge_kernel(const float* __restrict__ E,
                 const float* __restrict__ be2,
                 float* __restrict__ out) {
    const int tid  = threadIdx.x;
    const int lane = tid & 31;
    const int warp = tid >> 5;
    const int wm   = warp >> 1;
    const int wn   = warp & 1;
    const int a0   = blockIdx.y * 16;
    const int b0   = blockIdx.x * 8;

    const uint32_t su = (uint32_t)__cvta_generic_to_shared(smem);
    const int lr  = lane & 15;
    const int lk8 = (lane >> 4) * 8;

    float acc[2][8][4];
#pragma unroll
    for (int mi = 0; mi < 2; mi++)
#pragma unroll
        for (int nf = 0; nf < 8; nf++)
#pragma unroll
            for (int c = 0; c < 4; c++) acc[mi][nf][c] = 0.f;

    // E LDG prefetch registers: one k32 chunk = 4 float4 per thread
    const int erow = tid >> 3;
    const int eq   = tid & 7;
    float4 rg[4];

#define LDG_E_CHUNK(kc) do { \
    _Pragma("unroll") \
    for (int u = 0; u < 4; u++) { \
        const int r = erow + 32 * u; \
        rg[u] = *reinterpret_cast<const float4*>( \
            E + ((size_t)(a0 + (r >> 3)) * 512 + (b0 + (r & 7))) * K1 + (kc) + eq * 4); \
    } } while (0)

// single STS.64 per segment (forced via uint2)
#define STS_E_CHUNK(buf) do { \
    char* eb = smem + OFF_E16 + (buf) * E16SZ; \
    _Pragma("unroll") \
    for (int u = 0; u < 4; u++) { \
        const int r = erow + 32 * u; \
        uint32_t lo = h2_bits(__floats2half2_rn(rg[u].x, rg[u].y)); \
        uint32_t hi = h2_bits(__floats2half2_rn(rg[u].z, rg[u].w)); \
        *reinterpret_cast<uint2*>(eb + ((size_t)r * ESTRIDE + eq * 4) * 2) = make_uint2(lo, hi); \
    } } while (0)

// 4-slot W1 ring: stage chunk ci2 into slot ci2&3 (distance 2 from live slot)
#define STAGE_W1(ci2) do { \
    const uint32_t sbase = su + OFF_W + ((ci2) & 3) * W1SLOT; \
    _Pragma("unroll") \
    for (int u = 0; u < 2; u++) { \
        const int ii = tid + u * 256; \
        const int rw = ii >> 4, sg = ii & 15; \
        cp_async16(sbase + rw * (WSTRIDE * 2) + sg * 16, \
                   reinterpret_cast<const char*>(g_W1h) + ((ci2) * 32 + rw) * 256 + sg * 16); \
    } cp_commit(); } while (0)

    // prologue
    LDG_E_CHUNK(0);
    STS_E_CHUNK(0);
    STAGE_W1(0);
    LDG_E_CHUNK(32);
    STAGE_W1(1);

    // ---------------- GEMM1: 8 chunks of k=32 ----------------
#pragma unroll 1
    for (int ci = 0; ci < 8; ci++) {
        if (ci < 7) cp_wait<1>(); else cp_wait<0>();
        __syncthreads();

        if (ci < 7) STS_E_CHUNK((ci + 1) & 1);
        if (ci + 2 < 8) {
            LDG_E_CHUNK((ci + 2) * 32);
            STAGE_W1(ci + 2);
        }

        const uint32_t ea = su + OFF_E16 + (ci & 1) * E16SZ;
        const uint32_t wb = su + OFF_W + (ci & 3) * W1SLOT;
#pragma unroll
        for (int s = 0; s < 2; s++) {
            uint32_t af0[4], af1[4];
            LDSM_X4(af0, ea + ((wm * 32 + lr) * ESTRIDE + s * 16 + lk8) * 2);
            LDSM_X4(af1, ea + ((wm * 32 + 16 + lr) * ESTRIDE + s * 16 + lk8) * 2);
#pragma unroll
            for (int q = 0; q < 4; q++) {
                uint32_t bf[4];
                LDSM_X4T(bf, wb + ((s * 16 + lr) * WSTRIDE + wn * 64 + q * 16 + lk8) * 2);
                MMA16816(acc[0][2 * q + 0], af0, bf + 0);
                MMA16816(acc[0][2 * q + 1], af0, bf + 2);
                MMA16816(acc[1][2 * q + 0], af1, bf + 0);
                MMA16816(acc[1][2 * q + 1], af1, bf + 2);
            }
        }
    }
    __syncthreads();   // all ldsm of E16 / W1 ring done everywhere

    // stage ALL of W2 into the (now dead) W region: contiguous rows, stride 136h
#pragma unroll
    for (int u = 0; u < 8; u++) {
        const int ii = tid + u * 256;          // 0..2047
        const int rw = ii >> 4, sg = ii & 15;  // rw 0..127
        cp_async16(su + OFF_W + rw * (WSTRIDE * 2) + sg * 16,
                   reinterpret_cast<const char*>(g_W2h) + rw * 256 + sg * 16);
    }
    cp_commit();

    // -------- epilogue 1: h = fp16(relu(acc + preA + preB)) -> smem h tile --------
    {
        const int colb = wn * 64 + 2 * (lane & 3);
#pragma unroll
        for (int mi = 0; mi < 2; mi++) {
            const int r1 = wm * 32 + mi * 16 + (lane >> 2);
            const int r2 = r1 + 8;
            const float* pA1 = g_preA + (size_t)(a0 + (r1 >> 3)) * ND;
            const float* pB1 = g_preB + (size_t)(b0 + (r1 & 7)) * ND;
            const float* pA2 = g_preA + (size_t)(a0 + (r2 >> 3)) * ND;
            const float* pB2 = g_preB + (size_t)(b0 + (r2 & 7)) * ND;
#pragma unroll
            for (int nf = 0; nf < 8; nf++) {
                const int col = colb + nf * 8;
                float2 qa1 = *reinterpret_cast<const float2*>(pA1 + col);
                float2 qb1 = *reinterpret_cast<const float2*>(pB1 + col);
                float2 qa2 = *reinterpret_cast<const float2*>(pA2 + col);
                float2 qb2 = *reinterpret_cast<const float2*>(pB2 + col);
                float v0 = fmaxf(acc[mi][nf][0] + qa1.x + qb1.x, 0.f);
                float v1 = fmaxf(acc[mi][nf][1] + qa1.y + qb1.y, 0.f);
                float v2 = fmaxf(acc[mi][nf][2] + qa2.x + qb2.x, 0.f);
                float v3 = fmaxf(acc[mi][nf][3] + qa2.y + qb2.y, 0.f);
                *reinterpret_cast<half2*>(smem + OFF_HT + ((size_t)r1 * HSTRIDE + col) * 2) =
                    __floats2half2_rn(v0, v1);
                *reinterpret_cast<half2*>(smem + OFF_HT + ((size_t)r2 * HSTRIDE + col) * 2) =
                    __floats2half2_rn(v2, v3);
            }
        }
    }
    // reset accumulators for GEMM2
#pragma unroll
    for (int mi = 0; mi < 2; mi++)
#pragma unroll
        for (int nf = 0; nf < 8; nf++)
#pragma unroll
            for (int c = 0; c < 4; c++) acc[mi][nf][c] = 0.f;

    cp_wait<0>();
    __syncthreads();   // h visible + W2 staged

    // ---------------- GEMM2: h(128x128) @ W2(128x128), no inner barriers ------
#pragma unroll
    for (int ks = 0; ks < 8; ks++) {
        uint32_t af0[4], af1[4];
        LDSM_X4(af0, su + OFF_HT + ((wm * 32 + lr) * HSTRIDE + ks * 16 + lk8) * 2);
        LDSM_X4(af1, su + OFF_HT + ((wm * 32 + 16 + lr) * HSTRIDE + ks * 16 + lk8) * 2);
#pragma unroll
        for (int q = 0; q < 4; q++) {
            uint32_t bf[4];
            LDSM_X4T(bf, su + OFF_W + ((ks * 16 + lr) * WSTRIDE + wn * 64 + q * 16 + lk8) * 2);
            MMA16816(acc[0][2 * q + 0], af0, bf + 0);
            MMA16816(acc[0][2 * q + 1], af0, bf + 2);
            MMA16816(acc[1][2 * q + 0], af1, bf + 0);
            MMA16816(acc[1][2 * q + 1], af1, bf + 2);
        }
    }

    // -------- epilogue 2: out = relu(acc + be2); sums (no smem atomics) --------
    {
        const int colb = wn * 64 + 2 * (lane & 3);
        float* sbw = reinterpret_cast<float*>(smem + OFF_SBW);   // [4][8][128]
        float sbx[8], sby[8];
#pragma unroll
        for (int nf = 0; nf < 8; nf++) { sbx[nf] = 0.f; sby[nf] = 0.f; }
#pragma unroll
        for (int mi = 0; mi < 2; mi++) {
#pragma unroll
            for (int hh = 0; hh < 2; hh++) {
                const int r = wm * 32 + mi * 16 + hh * 8 + (lane >> 2);
                const int ag = a0 + (r >> 3);
                float* orow = out + ((size_t)ag * 512 + (b0 + (r & 7))) * ND;
#pragma unroll
                for (int nf = 0; nf < 8; nf++) {
                    const int col = colb + nf * 8;
                    float2 be = *reinterpret_cast<const float2*>(be2 + col);
                    float v0 = fmaxf(acc[mi][nf][hh * 2 + 0] + be.x, 0.f);
                    float v1 = fmaxf(acc[mi][nf][hh * 2 + 1] + be.y, 0.f);
                    *reinterpret_cast<float2*>(orow + col) = make_float2(v0, v1);
                    sbx[nf] += v0; sby[nf] += v1;
                    float sx = v0, sy = v1;
                    sx += __shfl_xor_sync(0xffffffffu, sx, 4);
                    sy += __shfl_xor_sync(0xffffffffu, sy, 4);
                    sx += __shfl_xor_sync(0xffffffffu, sx, 8);
                    sy += __shfl_xor_sync(0xffffffffu, sy, 8);
                    sx += __shfl_xor_sync(0xffffffffu, sx, 16);
                    sy += __shfl_xor_sync(0xffffffffu, sy, 16);
                    if (lane < 4) {
                        atomicAdd(&g_sumA[(size_t)ag * ND + col], sx);
                        atomicAdd(&g_sumA[(size_t)ag * ND + col + 1], sy);
                    }
                }
            }
        }
        // per-wm slice write: warps (wm, wn=0/1) cover disjoint cols -> plain STS.64
        const int brow = lane >> 2;   // = b index within tile (constant over mi/hh)
#pragma unroll
        for (int nf = 0; nf < 8; nf++) {
            const int col = colb + nf * 8;
            *reinterpret_cast<float2*>(&sbw[(size_t)(wm * 8 + brow) * ND + col]) =
                make_float2(sbx[nf], sby[nf]);
        }
    }
    __syncthreads();
    // flush: sum the 4 wm-slices, one global atomic pass (vectorized 4-wide)
    {
        const float* sbw = reinterpret_cast<const float*>(smem + OFF_SBW);
        const int b  = tid >> 5;           // 0..7
        const int c4 = (tid & 31) * 4;     // 0,4,...,124
        float4 s0 = *reinterpret_cast<const float4*>(&sbw[(size_t)(0 * 8 + b) * ND + c4]);
        float4 s1 = *reinterpret_cast<const float4*>(&sbw[(size_t)(1 * 8 + b) * ND + c4]);
        float4 s2 = *reinterpret_cast<const float4*>(&sbw[(size_t)(2 * 8 + b) * ND + c4]);
        float4 s3 = *reinterpret_cast<const float4*>(&sbw[(size_t)(3 * 8 + b) * ND + c4]);
        float* dst = &g_sumB[(size_t)(b0 + b) * ND + c4];
        atomicAdd(dst + 0, s0.x + s1.x + s2.x + s3.x);
        atomicAdd(dst + 1, s0.y + s1.y + s2.y + s3.y);
        atomicAdd(dst + 2, s0.z + s1.z + s2.z + s3.z);
        atomicAdd(dst + 3, s0.w + s1.w + s2.w + s3.w);
    }
}

// ---------------------------------------------------------------------------
// Final node MLP: rows 0..511 = nodes_a, 512..1023 = nodes_b
// ---------------------------------------------------------------------------
__global__ void nodes_kernel(const float* __restrict__ na,
                             const float* __restrict__ nb,
                             const float* __restrict__ Wn1,
                             const float* __restrict__ bn1,
                             const float* __restrict__ Wn2,
                             const float* __restrict__ bn2,
                             float* __restrict__ out) {
    __shared__ float x[2 * ND];
    __shared__ float h[ND];
    const int row = blockIdx.x;
    const int n   = threadIdx.x;
    const int idx = row & 511;
    const float* emb  = (row < 512) ? na : nb;
    const float* sums = (row < 512) ? g_sumA : g_sumB;
    x[n]      = emb[idx * ND + n];
    x[ND + n] = sums[idx * ND + n];
    __syncthreads();
    float v = bn1[n];
#pragma unroll 8
    for (int k = 0; k < 2 * ND; k++) v += x[k] * Wn1[k * ND + n];
    h[n] = fmaxf(v, 0.f);
    __syncthreads();
    float v2 = bn2[n];
#pragma unroll 8
    for (int k = 0; k < ND; k++) v2 += h[k] * Wn2[k * ND + n];
    out[(size_t)NA * NB * ND + (size_t)row * ND + n] = fmaxf(v2, 0.f);
}

// ---------------------------------------------------------------------------
extern "C" void kernel_launch(void* const* d_in, const int* in_sizes, int n_in,
                              void* d_out, int out_size) {
    const float* E   = (const float*)d_in[0];
    const float* na  = (const float*)d_in[1];
    const float* nb  = (const float*)d_in[2];
    const float* We1 = (const float*)d_in[3];
    const float* be1 = (const float*)d_in[4];
    const float* We2 = (const float*)d_in[5];
    const float* be2 = (const float*)d_in[6];
    const float* Wn1 = (const float*)d_in[7];
    const float* bn1 = (const float*)d_in[8];
    const float* Wn2 = (const float*)d_in[9];
    const float* bn2 = (const float*)d_in[10];
    float* out = (float*)d_out;

    cudaFuncSetAttribute(edge_kernel, cudaFuncAttributeMaxDynamicSharedMemorySize, SMEM_BYTES);

    // edge_kernel at launch index 3 -> profiled by ncu (-s 5 -c 1)
    wconv_kernel<<<256, 128>>>(We1, We2);
    pre_kernel<<<512, 128>>>(na, nb, We1, be1);
    zsum_kernel<<<512, 128>>>();
    edge_kernel<<<dim3(64, 32), 256, SMEM_BYTES>>>(E, be2, out);
    nodes_kernel<<<1024, 128>>>(na, nb, Wn1, bn1, Wn2, bn2, out);
}